// round 16
// baseline (speedup 1.0000x reference)
#include <cuda_runtime.h>
#include <cuda_fp16.h>
#include <cstdint>
#include <math.h>

// ---------------------------------------------------------------------------
// Problem constants
// ---------------------------------------------------------------------------
#define VEG 4
#define WEA 8
#define HID 512
#define NB  256
#define T_HIST 150
#define T_FUT  50
#define HB (NB * HID)
#define XPW 128           // padded x width (12 real + 116 zeros) = one K-chunk
#define GROW 2048         // gate rows (4*HID)
#define NTHREADS 256      // 8 warps per CTA, occupancy 2
#define NCTA 256          // persistent grid (all co-resident at occ 2)

// ---------------------------------------------------------------------------
// Device scratch (static only) — pure fp16 activations and weights
// ---------------------------------------------------------------------------
__device__ __half g_xp[T_HIST * NB * XPW];
__device__ __half g_xd[NB * XPW];
__device__ float g_pred[NB * VEG];
__device__ __half g_y0[T_HIST * HB];     // layer0 outputs (h-chain)
__device__ __half g_zb[HB];              // fp16 zeros
__device__ float g_c0[HB];
__device__ float g_c1[HB];
__device__ __half g_h1[2 * HB];
__device__ __half g_h0[2 * HB];
__device__ float g_h1f[HB];
// reordered (row = u*4+g) fp16 weights
__device__ __half g_w0[GROW * HID];      // Whh0
__device__ __half g_w1hh[GROW * HID];    // Whh1
__device__ __half g_w1ih[GROW * HID];    // Wih1
__device__ __half g_wx0[GROW * XPW];     // Wih0 padded to 128
__device__ float g_br0[GROW], g_br1[GROW];
// grid barrier state
__device__ unsigned g_cnt = 0;
__device__ unsigned g_gen = 0;

// ---------------------------------------------------------------------------
// Portable PTX helpers (sm_80+ only)
// ---------------------------------------------------------------------------
__device__ __forceinline__ uint32_t smem_u32(const void* p) {
    uint32_t a;
    asm("{ .reg .u64 t; cvta.to.shared.u64 t, %1; cvt.u32.u64 %0, t; }"
        : "=r"(a) : "l"(p));
    return a;
}
#define CP_ASYNC16(dst, src) \
    asm volatile("cp.async.cg.shared.global [%0], [%1], 16;" \
                 :: "r"(dst), "l"(src) : "memory")
#define CP_COMMIT() asm volatile("cp.async.commit_group;" ::: "memory")
#define CP_WAIT1()  asm volatile("cp.async.wait_group 1;" ::: "memory")
#define CP_WAIT0()  asm volatile("cp.async.wait_group 0;" ::: "memory")

#define LDM4(r, addr) \
    asm volatile("ldmatrix.sync.aligned.m8n8.x4.shared.b16 {%0,%1,%2,%3}, [%4];" \
                 : "=r"((r)[0]), "=r"((r)[1]), "=r"((r)[2]), "=r"((r)[3]) \
                 : "r"(addr))

#define MMA16816F(d, a, b0, b1) \
    asm volatile( \
        "mma.sync.aligned.m16n8k16.row.col.f32.f16.f16.f32 " \
        "{%0,%1,%2,%3}, {%4,%5,%6,%7}, {%8,%9}, {%0,%1,%2,%3};" \
        : "+f"((d)[0]), "+f"((d)[1]), "+f"((d)[2]), "+f"((d)[3]) \
        : "r"((a)[0]), "r"((a)[1]), "r"((a)[2]), "r"((a)[3]), \
          "r"(b0), "r"(b1))

// ---------------------------------------------------------------------------
// Grid barrier (all NCTA CTAs co-resident)
// ---------------------------------------------------------------------------
__device__ __forceinline__ void grid_bar() {
    __syncthreads();
    if (threadIdx.x == 0) {
        __threadfence();
        unsigned gen = *(volatile unsigned*)&g_gen;
        if (atomicAdd(&g_cnt, 1u) == NCTA - 1) {
            g_cnt = 0;
            __threadfence();
            atomicAdd(&g_gen, 1u);
        } else {
            while (*(volatile unsigned*)&g_gen == gen) __nanosleep(64);
        }
        __threadfence();
    }
    __syncthreads();
}

// ---------------------------------------------------------------------------
// SMEM layout: K=128 chunks.  A(MT x 128) + B(64 x 128), 3 stages.
// Row stride 136 fp16 = 272B: ldmatrix 8-row phases hit all 32 banks once.
// ---------------------------------------------------------------------------
#define SM_STRIDE 136                       // fp16 elems/row
#define ROW_B (SM_STRIDE * 2)               // 272 bytes
#define B_TILE_BYTES (64 * ROW_B)           // 17408
#define NSTAGE 3
#define CS_STRIDE 68                        // fp32 C tile row stride

#define A_TILE_BYTES_(MT) ((MT) * ROW_B)
#define STAGE_BYTES_(MT)  (A_TILE_BYTES_(MT) + B_TILE_BYTES)
#define OFF_BIAS_(MT)     (NSTAGE * STAGE_BYTES_(MT))
#define SMEM_TOTAL_(MT)   (OFF_BIAS_(MT) + 64 * 4 + 16)
// MT=64: stage 34816, total 104720 -> 2/SM = 209KB <= 228KB
// MT=32: stage 26112, total 78608  -> 2/SM = 157KB

// ---------------------------------------------------------------------------
// Math helpers
// ---------------------------------------------------------------------------
__device__ __forceinline__ float sigmoidf_(float x) { return 1.0f / (1.0f + __expf(-x)); }
__device__ __forceinline__ float tanhf_(float x)    { return 2.0f / (1.0f + __expf(-2.0f * x)) - 1.0f; }

// ---------------------------------------------------------------------------
// prep: smoothing + padded-x fp16 for encoder; decoder init at t=149
// ---------------------------------------------------------------------------
__global__ void prep_kernel(const float* __restrict__ veg,
                            const float* __restrict__ wh,
                            const float* __restrict__ wf,
                            __half* __restrict__ xp,
                            __half* __restrict__ xd,
                            float* __restrict__ pred) {
    int b = threadIdx.x;
    int t = blockIdx.x;
    const int base = (t * NB + b) * XPW;
    float vs[VEG];
#pragma unroll
    for (int v = 0; v < VEG; v++) {
        float val = veg[b * (T_HIST * VEG) + t * VEG + v];
        float s = 0.f;
#pragma unroll
        for (int dt = -2; dt <= 2; dt++) {
            int tt = t + dt;
            if (tt >= 0 && tt < T_HIST) {
                float u = veg[b * (T_HIST * VEG) + tt * VEG + v];
                if (!isnan(u)) s += u;
            }
        }
        float sm = s * 0.2f;
        float outv = isnan(val) ? sm : val;
        if (isnan(outv)) outv = 0.f;
        vs[v] = outv;
        xp[base + v] = __float2half(outv);
    }
#pragma unroll
    for (int k = 0; k < WEA; k++)
        xp[base + VEG + k] = __float2half(wh[b * (T_HIST * WEA) + t * WEA + k]);
    __half z = __float2half(0.f);
    for (int c = VEG + WEA; c < XPW; c++) xp[base + c] = z;

    if (t == T_HIST - 1) {
        int db = b * XPW;
#pragma unroll
        for (int v = 0; v < VEG; v++) {
            pred[b * VEG + v] = vs[v];
            xd[db + v] = __float2half(vs[v]);
        }
#pragma unroll
        for (int k = 0; k < WEA; k++)
            xd[db + VEG + k] = __float2half(wf[b * (T_FUT * WEA) + k]);
        for (int c = VEG + WEA; c < XPW; c++) xd[db + c] = z;
    }
}

// ---------------------------------------------------------------------------
// weight prep: reorder rows to u*4+g, fp16, pad Wih0 to 128 cols
// ---------------------------------------------------------------------------
__global__ void wprep_kernel(const float* __restrict__ Wih0, const float* __restrict__ Whh0,
                             const float* __restrict__ b0,   const float* __restrict__ Wih1,
                             const float* __restrict__ Whh1, const float* __restrict__ b1,
                             __half* w0, __half* w1hh, __half* w1ih, __half* wx0,
                             float* br0, float* br1) {
    int rn = blockIdx.x;                       // new row
    int orig = (rn & 3) * HID + (rn >> 2);     // g*512 + u
    for (int c = threadIdx.x; c < HID; c += blockDim.x) {
        w0[rn * HID + c]   = __float2half(Whh0[orig * HID + c]);
        w1hh[rn * HID + c] = __float2half(Whh1[orig * HID + c]);
        w1ih[rn * HID + c] = __float2half(Wih1[orig * HID + c]);
    }
    for (int c = threadIdx.x; c < XPW; c += blockDim.x) {
        float v = (c < VEG + WEA) ? Wih0[orig * (VEG + WEA) + c] : 0.f;
        wx0[rn * XPW + c] = __float2half(v);
    }
    if (threadIdx.x == 0) { br0[rn] = b0[orig]; br1[rn] = b1[orig]; }
}

__global__ void zero_kernel(float* __restrict__ c0, float* __restrict__ c1,
                            __half* __restrict__ zb) {
    int i = blockIdx.x * blockDim.x + threadIdx.x;
    if (i < HB) { c0[i] = 0.f; c1[i] = 0.f; zb[i] = __float2half(0.f); }
}

// ---------------------------------------------------------------------------
// Cell body: one MT(batch)x64(gate) tile, fp16 HMMA, K=128 chunks.
// 8 warps: (MT/32) M x 2 N x KS K-groups, warp tile 32x32; KITER = 8/KS.
// ncx = x-part chunk count (1 for L0 [128-wide x], 4 for L1 [512-wide]).
// ---------------------------------------------------------------------------
template <int MT>
__device__ __forceinline__ void cell_body(
    char* smem, int m0, int tileY,
    const __half* __restrict__ Ah, const __half* __restrict__ Bh,   // h, Whh
    const __half* __restrict__ Ax, const __half* __restrict__ Bx,   // x, Wx
    int ncx, int ldx,
    const float* __restrict__ biasr,
    float* __restrict__ c, float* __restrict__ hf,
    __half* __restrict__ hout) {

    constexpr int A_TILE = A_TILE_BYTES_(MT);
    constexpr int STAGE  = STAGE_BYTES_(MT);
    constexpr int OFF_A  = 0;
    constexpr int OFF_B  = A_TILE;
    constexpr int OFF_BIAS = OFF_BIAS_(MT);
    constexpr int WM = MT / 32;           // M warp-slices (1 or 2)
    constexpr int KS = 8 / (WM * 2);      // K-groups (4 or 2)
    constexpr int KITER = 8 / KS;         // 16-wide k-slices per warp per chunk
    constexpr int CSLAB = MT * CS_STRIDE; // floats per K-group C slab
    static_assert(WM * 2 * KS == 8, "warp layout");

    const uint32_t sbase = smem_u32(smem);
    const int tid = threadIdx.x;
    const int warp = tid >> 5;
    const int lane = tid & 31;
    const int n0 = tileY * 64;            // reordered weight row base
    const int u0 = tileY * 16;            // unit base
    const int ks = warp % KS;
    const int rem = warp / KS;
    const int wn = rem & 1;               // 0..1 (32-col slices)
    const int wm = rem >> 1;              // 0..WM-1 (32-row slices)

    if (tid < 64)
        *reinterpret_cast<float*>(smem + OFF_BIAS + tid * 4) = biasr[n0 + tid];

    float cf[2][4][4];
#pragma unroll
    for (int mi = 0; mi < 2; mi++)
#pragma unroll
        for (int nj = 0; nj < 4; nj++)
#pragma unroll
            for (int r = 0; r < 4; r++) cf[mi][nj][r] = 0.f;

    const int NC = 4 + ncx;               // 4 h-chunks + x-chunks (K=128 each)

    auto prefetch = [&](int ch) {
        const __half *aP, *bP;
        int lda, k0;
        if (ch < 4) { aP = Ah; bP = Bh; lda = HID; k0 = ch * 128; }
        else        { aP = Ax; bP = Bx; lda = ldx; k0 = (ch - 4) * 128; }
        const uint32_t st = sbase + (ch % NSTAGE) * STAGE;
        // A: MT rows x 128 fp16 (MT*16 16B chunks)
#pragma unroll
        for (int i = 0; i < (MT * 16) / NTHREADS; i++) {
            int idx = tid + i * NTHREADS;
            int r = idx >> 4, q = idx & 15;
            uint32_t off = r * ROW_B + q * 16;
            long ao = (long)(m0 + r) * lda + k0 + q * 8;
            CP_ASYNC16(st + OFF_A + off, aP + ao);
        }
        // B: 64 rows x 128 fp16 (1024 16B chunks)
#pragma unroll
        for (int i = 0; i < 1024 / NTHREADS; i++) {
            int idx = tid + i * NTHREADS;
            int r = idx >> 4, q = idx & 15;
            uint32_t off = r * ROW_B + q * 16;
            long bo = (long)(n0 + r) * lda + k0 + q * 8;
            CP_ASYNC16(st + OFF_B + off, bP + bo);
        }
    };

    prefetch(0); CP_COMMIT();
    prefetch(1); CP_COMMIT();

    for (int ch = 0; ch < NC; ch++) {
        if (ch + 1 < NC) CP_WAIT1(); else CP_WAIT0();
        __syncthreads();                    // publishes chunk ch
        if (ch + 2 < NC) { prefetch(ch + 2); CP_COMMIT(); }

        const uint32_t base = sbase + (ch % NSTAGE) * STAGE;
#pragma unroll
        for (int ki = 0; ki < KITER; ki++) {
            const int kk = (ks * KITER + ki) * 16;
            uint32_t ah[2][4], bh[4][2];
#pragma unroll
            for (int mi = 0; mi < 2; mi++) {
                uint32_t roff =
                    (uint32_t)((wm * 32 + mi * 16 + (lane & 15)) * ROW_B +
                               (kk + (lane >> 4) * 8) * 2);
                LDM4(ah[mi], base + OFF_A + roff);
            }
#pragma unroll
            for (int p = 0; p < 2; p++) {
                uint32_t roff =
                    (uint32_t)((wn * 32 + p * 16 + (lane & 15)) * ROW_B +
                               (kk + (lane >> 4) * 8) * 2);
                uint32_t rb[4];
                LDM4(rb, base + OFF_B + roff);
                bh[p * 2 + 0][0] = rb[0]; bh[p * 2 + 0][1] = rb[2];
                bh[p * 2 + 1][0] = rb[1]; bh[p * 2 + 1][1] = rb[3];
            }
#pragma unroll
            for (int mi = 0; mi < 2; mi++)
#pragma unroll
                for (int nj = 0; nj < 4; nj++)
                    MMA16816F(cf[mi][nj], ah[mi], bh[nj][0], bh[nj][1]);
        }
    }
    __syncthreads();   // all ldmatrix reads done before Cs overwrites stage 0

    // ---- epilogue: per-K-group C slabs (single barrier) ----
    float* Cs = reinterpret_cast<float*>(smem);   // KS slabs of MT x CS_STRIDE
    {
        float* Cg = Cs + ks * CSLAB;
#pragma unroll
        for (int mi = 0; mi < 2; mi++)
#pragma unroll
            for (int nj = 0; nj < 4; nj++) {
                int r = wm * 32 + mi * 16 + (lane >> 2);
                int col = wn * 32 + nj * 8 + (lane & 3) * 2;
                Cg[r * CS_STRIDE + col]           = cf[mi][nj][0];
                Cg[r * CS_STRIDE + col + 1]       = cf[mi][nj][1];
                Cg[(r + 8) * CS_STRIDE + col]     = cf[mi][nj][2];
                Cg[(r + 8) * CS_STRIDE + col + 1] = cf[mi][nj][3];
            }
    }
    __syncthreads();

    const float* Bs = reinterpret_cast<const float*>(smem + OFF_BIAS);
#pragma unroll
    for (int k = 0; k < (MT * 16) / NTHREADS; k++) {
        int id = tid + k * NTHREADS;
        int u = id & 15, bb = id >> 4;        // bb 0..MT-1
        float4 g4 = *reinterpret_cast<const float4*>(&Cs[bb * CS_STRIDE + u * 4]);
#pragma unroll
        for (int g = 1; g < KS; g++) {
            float4 p4 = *reinterpret_cast<const float4*>(
                &Cs[g * CSLAB + bb * CS_STRIDE + u * 4]);
            g4.x += p4.x; g4.y += p4.y; g4.z += p4.z; g4.w += p4.w;
        }
        float gi = sigmoidf_(g4.x + Bs[u * 4 + 0]);
        float gf = sigmoidf_(g4.y + Bs[u * 4 + 1]);
        float gg = tanhf_   (g4.z + Bs[u * 4 + 2]);
        float go = sigmoidf_(g4.w + Bs[u * 4 + 3]);
        int gidx = (m0 + bb) * HID + u0 + u;
        float cn = gf * c[gidx] + gi * gg;
        c[gidx] = cn;
        float hv = go * tanhf_(cn);
        if (hf) hf[gidx] = hv;
        hout[gidx] = __float2half(hv);
    }
}

// ---------------------------------------------------------------------------
// THE persistent kernel: whole network after prep. 256 CTAs, occ 2,
// software grid barriers between dependent phases.
// ---------------------------------------------------------------------------
__global__ void __launch_bounds__(NTHREADS, 2)
lstm_persist(const __half* __restrict__ xp, __half* __restrict__ xd,
             const __half* __restrict__ zb,
             const __half* __restrict__ w0,   const __half* __restrict__ wx0,
             const float* __restrict__ br0,  float* __restrict__ c0,
             const __half* __restrict__ w1hh, const __half* __restrict__ w1ih,
             const float* __restrict__ br1,  float* __restrict__ c1,
             __half* __restrict__ y0, __half* __restrict__ h1,
             __half* __restrict__ h0, float* __restrict__ h1f,
             const float* __restrict__ headW, const float* __restrict__ headb,
             const float* __restrict__ wf,
             float* __restrict__ pred, float* __restrict__ out) {
    extern __shared__ __align__(16) char smem[];
    const int bid = blockIdx.x;

    // ===== encoder: L1 on CTAs 0..127 (4x32 tiles, MT=64), L0 on 128..255 ====
    {
        const bool isL1 = bid < 128;
        const int rem = isL1 ? bid : bid - 128;
        const int m0 = (rem >> 5) * 64;
        const int yt = rem & 31;

        if (!isL1)   // L0(0): A = zeros, X = xp[0]
            cell_body<64>(smem, m0, yt, zb, w0, xp, wx0,
                          1, XPW, br0, c0, nullptr, y0);
        grid_bar();

        for (int t = 0; t < T_HIST; t++) {      // t = 0..149
            if (isL1) {
                const __half* h1p = (t == 0) ? zb : (h1 + ((t + 1) & 1) * HB);
                cell_body<64>(smem, m0, yt, h1p, w1hh,
                              y0 + (size_t)t * HB, w1ih,
                              4, HID, br1, c1, nullptr, h1 + (t & 1) * HB);
            } else if (t < T_HIST - 1) {
                cell_body<64>(smem, m0, yt, y0 + (size_t)t * HB, w0,
                              xp + (size_t)(t + 1) * NB * XPW, wx0,
                              1, XPW, br0, c0, nullptr,
                              y0 + (size_t)(t + 1) * HB);
            }
            grid_bar();
        }
    }

    // ===== decoder: all 256 CTAs (8x32 tiles, MT=32); 3 phases per step =====
    {
        const int m0 = (bid >> 5) * 32;
        const int yt = bid & 31;
        for (int t = 0; t < T_FUT; t++) {
            // L0(t): A = h0 prev (or y0[149]), X = xd
            const __half* hp = (t == 0) ? (y0 + (size_t)(T_HIST - 1) * HB)
                                        : (h0 + ((t + 1) & 1) * HB);
            cell_body<32>(smem, m0, yt, hp, w0, xd, wx0,
                          1, XPW, br0, c0, nullptr, h0 + (t & 1) * HB);
            grid_bar();
            // L1(t): A = h1 prev (enc ended at index 1; read (t+1)&1, write t&1)
            cell_body<32>(smem, m0, yt, h1 + ((t + 1) & 1) * HB, w1hh,
                          h0 + (t & 1) * HB, w1ih,
                          4, HID, br1, c1, h1f, h1 + (t & 1) * HB);
            grid_bar();
            // head: CTA bid handles batch b = bid
            {
                const int b = bid;
                if (threadIdx.x < 128) {
                    int w = threadIdx.x >> 5;
                    int lane = threadIdx.x & 31;
                    const float* hr = h1f + b * HID;
                    const float* wr = headW + w * HID;
                    float s = 0.f;
                    for (int k = lane; k < HID; k += 32)
                        s += __ldcg(hr + k) * wr[k];   // L1-bypass: cross-CTA
#pragma unroll
                    for (int o = 16; o; o >>= 1)
                        s += __shfl_down_sync(0xffffffffu, s, o);
                    if (lane == 0) {
                        float p = pred[b * VEG + w] + s + headb[w];
                        pred[b * VEG + w] = p;
                        out[b * (T_FUT * VEG) + t * VEG + w] = p;
                        xd[b * XPW + w] = __float2half(p);
                    }
                    if (threadIdx.x < WEA && t + 1 < T_FUT)
                        xd[b * XPW + VEG + threadIdx.x] = __float2half(
                            wf[b * (T_FUT * WEA) + (t + 1) * WEA + threadIdx.x]);
                }
            }
            grid_bar();
        }
    }
}

// ---------------------------------------------------------------------------
// Host launcher (single stream — graph-capture safe; ONE main kernel)
// ---------------------------------------------------------------------------
extern "C" void kernel_launch(void* const* d_in, const int* in_sizes, int n_in,
                              void* d_out, int out_size) {
    const float* veg   = (const float*)d_in[0];
    const float* wh    = (const float*)d_in[1];
    const float* wf    = (const float*)d_in[2];
    const float* Wih0  = (const float*)d_in[3];
    const float* Whh0  = (const float*)d_in[4];
    const float* b0    = (const float*)d_in[5];
    const float* Wih1  = (const float*)d_in[6];
    const float* Whh1  = (const float*)d_in[7];
    const float* b1    = (const float*)d_in[8];
    const float* headW = (const float*)d_in[9];
    const float* headb = (const float*)d_in[10];
    float* out = (float*)d_out;

    __half *xp, *xd, *y0, *zb, *h1, *h0;
    __half *w0, *w1hh, *w1ih, *wx0;
    float *pred, *c0, *c1, *h1f, *br0, *br1;
    cudaGetSymbolAddress((void**)&xp,    g_xp);
    cudaGetSymbolAddress((void**)&xd,    g_xd);
    cudaGetSymbolAddress((void**)&pred,  g_pred);
    cudaGetSymbolAddress((void**)&y0,    g_y0);
    cudaGetSymbolAddress((void**)&zb,    g_zb);
    cudaGetSymbolAddress((void**)&c0,    g_c0);
    cudaGetSymbolAddress((void**)&c1,    g_c1);
    cudaGetSymbolAddress((void**)&h1,    g_h1);
    cudaGetSymbolAddress((void**)&h0,    g_h0);
    cudaGetSymbolAddress((void**)&h1f,   g_h1f);
    cudaGetSymbolAddress((void**)&w0,    g_w0);
    cudaGetSymbolAddress((void**)&w1hh,  g_w1hh);
    cudaGetSymbolAddress((void**)&w1ih,  g_w1ih);
    cudaGetSymbolAddress((void**)&wx0,   g_wx0);
    cudaGetSymbolAddress((void**)&br0,   g_br0);
    cudaGetSymbolAddress((void**)&br1,   g_br1);

    cudaFuncSetAttribute(lstm_persist,
                         cudaFuncAttributeMaxDynamicSharedMemorySize,
                         SMEM_TOTAL_(64));

    prep_kernel<<<T_HIST, NB>>>(veg, wh, wf, xp, xd, pred);
    wprep_kernel<<<GROW, 128>>>(Wih0, Whh0, b0, Wih1, Whh1, b1,
                                w0, w1hh, w1ih, wx0, br0, br1);
    zero_kernel<<<(HB + 255) / 256, 256>>>(c0, c1, zb);

    lstm_persist<<<NCTA, NTHREADS, SMEM_TOTAL_(64)>>>(
        xp, xd, zb,
        w0, wx0, br0, c0,
        w1hh, w1ih, br1, c1,
        y0, h1, h0, h1f,
        headW, headb, wf, pred, out);
}

// round 17
// speedup vs baseline: 1.0215x; 1.0215x over previous
#include <cuda_runtime.h>
#include <cuda_fp16.h>
#include <cstdint>
#include <math.h>

// ---------------------------------------------------------------------------
// Problem constants
// ---------------------------------------------------------------------------
#define VEG 4
#define WEA 8
#define HID 512
#define NB  256
#define T_HIST 150
#define T_FUT  50
#define HB (NB * HID)
#define XPW 64            // padded x width (12 real + 52 zeros)
#define GROW 2048         // gate rows (4*HID)
#define NTHREADS 256      // 8 warps per CTA, occupancy 2
#define NCTA 256          // persistent grid (all co-resident at occ 2)

// ---------------------------------------------------------------------------
// Device scratch (static only) — pure fp16 activations and weights
// ---------------------------------------------------------------------------
__device__ __half g_xp[T_HIST * NB * XPW];
__device__ __half g_xd[NB * XPW];
__device__ float g_pred[NB * VEG];
__device__ __half g_y0[T_HIST * HB];     // layer0 outputs (h-chain)
__device__ __half g_zb[HB];              // fp16 zeros
__device__ float g_c0[HB];
__device__ float g_c1[HB];
__device__ __half g_h1[2 * HB];
__device__ __half g_h0[2 * HB];
__device__ float g_h1f[HB];
// reordered (row = u*4+g) fp16 weights
__device__ __half g_w0[GROW * HID];      // Whh0
__device__ __half g_w1hh[GROW * HID];    // Whh1
__device__ __half g_w1ih[GROW * HID];    // Wih1
__device__ __half g_wx0[GROW * XPW];     // Wih0 padded
__device__ float g_br0[GROW], g_br1[GROW];
// grid barrier state (monotonic across launches — replay-safe by design)
__device__ unsigned g_gen = 0;
__device__ unsigned g_flags[NCTA * 32];  // one 128B line per CTA

// ---------------------------------------------------------------------------
// Portable PTX helpers (sm_80+ only)
// ---------------------------------------------------------------------------
__device__ __forceinline__ uint32_t smem_u32(const void* p) {
    uint32_t a;
    asm("{ .reg .u64 t; cvta.to.shared.u64 t, %1; cvt.u32.u64 %0, t; }"
        : "=r"(a) : "l"(p));
    return a;
}
#define CP_ASYNC16(dst, src) \
    asm volatile("cp.async.cg.shared.global [%0], [%1], 16;" \
                 :: "r"(dst), "l"(src) : "memory")
#define CP_COMMIT() asm volatile("cp.async.commit_group;" ::: "memory")
#define CP_WAIT1()  asm volatile("cp.async.wait_group 1;" ::: "memory")
#define CP_WAIT0()  asm volatile("cp.async.wait_group 0;" ::: "memory")

#define LDM4(r, addr) \
    asm volatile("ldmatrix.sync.aligned.m8n8.x4.shared.b16 {%0,%1,%2,%3}, [%4];" \
                 : "=r"((r)[0]), "=r"((r)[1]), "=r"((r)[2]), "=r"((r)[3]) \
                 : "r"(addr))

#define MMA16816F(d, a, b0, b1) \
    asm volatile( \
        "mma.sync.aligned.m16n8k16.row.col.f32.f16.f16.f32 " \
        "{%0,%1,%2,%3}, {%4,%5,%6,%7}, {%8,%9}, {%0,%1,%2,%3};" \
        : "+f"((d)[0]), "+f"((d)[1]), "+f"((d)[2]), "+f"((d)[3]) \
        : "r"((a)[0]), "r"((a)[1]), "r"((a)[2]), "r"((a)[3]), \
          "r"(b0), "r"(b1))

// ---------------------------------------------------------------------------
// Fast grid barrier: per-CTA flag lines (no atomic contention).
// CTA 0's threads poll one flag each in parallel, then publish g_gen.
// gen is a caller-held counter starting from g_gen's value at kernel entry,
// so stale state from prior launches/replays can never satisfy a wait.
// ---------------------------------------------------------------------------
__device__ __forceinline__ void grid_bar(unsigned& gen) {
    gen++;
    __syncthreads();
    if (blockIdx.x == 0) {
        if (threadIdx.x > 0 && threadIdx.x < NCTA) {
            while (((volatile unsigned*)g_flags)[threadIdx.x * 32] < gen)
                __nanosleep(20);
        }
        __syncthreads();
        if (threadIdx.x == 0) {
            __threadfence();
            *((volatile unsigned*)&g_gen) = gen;
        }
        __syncthreads();
    } else {
        if (threadIdx.x == 0) {
            __threadfence();
            ((volatile unsigned*)g_flags)[blockIdx.x * 32] = gen;
            while (*((volatile unsigned*)&g_gen) < gen) __nanosleep(20);
            __threadfence();
        }
        __syncthreads();
    }
}

// ---------------------------------------------------------------------------
// SMEM layout: A + B, 3 stages (K=64 chunks — R15-proven)
// ---------------------------------------------------------------------------
#define SM_STRIDE 72                        // fp16 elems/row (144B, conflict-free)
#define ROW_B (SM_STRIDE * 2)               // 144 bytes
#define B_TILE_BYTES (64 * ROW_B)           // 9216
#define NSTAGE 3
#define CS_STRIDE 68                        // fp32 C tile row stride

#define A_TILE_BYTES_(MT) ((MT) * ROW_B)
#define STAGE_BYTES_(MT)  (A_TILE_BYTES_(MT) + B_TILE_BYTES)
#define OFF_BIAS_(MT)     (NSTAGE * STAGE_BYTES_(MT))
#define SMEM_TOTAL_(MT)   (OFF_BIAS_(MT) + 64 * 4 + 16)
// MT=64: stage 18432, total 55568 -> 2 CTAs/SM fits

// ---------------------------------------------------------------------------
// Math helpers
// ---------------------------------------------------------------------------
__device__ __forceinline__ float sigmoidf_(float x) { return 1.0f / (1.0f + __expf(-x)); }
__device__ __forceinline__ float tanhf_(float x)    { return 2.0f / (1.0f + __expf(-2.0f * x)) - 1.0f; }

// ---------------------------------------------------------------------------
// prep: smoothing + padded-x fp16 for encoder; decoder init at t=149
// ---------------------------------------------------------------------------
__global__ void prep_kernel(const float* __restrict__ veg,
                            const float* __restrict__ wh,
                            const float* __restrict__ wf,
                            __half* __restrict__ xp,
                            __half* __restrict__ xd,
                            float* __restrict__ pred) {
    int b = threadIdx.x;
    int t = blockIdx.x;
    const int base = (t * NB + b) * XPW;
    float vs[VEG];
#pragma unroll
    for (int v = 0; v < VEG; v++) {
        float val = veg[b * (T_HIST * VEG) + t * VEG + v];
        float s = 0.f;
#pragma unroll
        for (int dt = -2; dt <= 2; dt++) {
            int tt = t + dt;
            if (tt >= 0 && tt < T_HIST) {
                float u = veg[b * (T_HIST * VEG) + tt * VEG + v];
                if (!isnan(u)) s += u;
            }
        }
        float sm = s * 0.2f;
        float outv = isnan(val) ? sm : val;
        if (isnan(outv)) outv = 0.f;
        vs[v] = outv;
        xp[base + v] = __float2half(outv);
    }
#pragma unroll
    for (int k = 0; k < WEA; k++)
        xp[base + VEG + k] = __float2half(wh[b * (T_HIST * WEA) + t * WEA + k]);
    __half z = __float2half(0.f);
    for (int c = VEG + WEA; c < XPW; c++) xp[base + c] = z;

    if (t == T_HIST - 1) {
        int db = b * XPW;
#pragma unroll
        for (int v = 0; v < VEG; v++) {
            pred[b * VEG + v] = vs[v];
            xd[db + v] = __float2half(vs[v]);
        }
#pragma unroll
        for (int k = 0; k < WEA; k++)
            xd[db + VEG + k] = __float2half(wf[b * (T_FUT * WEA) + k]);
        for (int c = VEG + WEA; c < XPW; c++) xd[db + c] = z;
    }
}

// ---------------------------------------------------------------------------
// weight prep: reorder rows to u*4+g, fp16, pad Wih0 to 64 cols
// ---------------------------------------------------------------------------
__global__ void wprep_kernel(const float* __restrict__ Wih0, const float* __restrict__ Whh0,
                             const float* __restrict__ b0,   const float* __restrict__ Wih1,
                             const float* __restrict__ Whh1, const float* __restrict__ b1,
                             __half* w0, __half* w1hh, __half* w1ih, __half* wx0,
                             float* br0, float* br1) {
    int rn = blockIdx.x;                       // new row
    int orig = (rn & 3) * HID + (rn >> 2);     // g*512 + u
    for (int c = threadIdx.x; c < HID; c += blockDim.x) {
        w0[rn * HID + c]   = __float2half(Whh0[orig * HID + c]);
        w1hh[rn * HID + c] = __float2half(Whh1[orig * HID + c]);
        w1ih[rn * HID + c] = __float2half(Wih1[orig * HID + c]);
    }
    if (threadIdx.x < XPW) {
        int c = threadIdx.x;
        float v = (c < VEG + WEA) ? Wih0[orig * (VEG + WEA) + c] : 0.f;
        wx0[rn * XPW + c] = __float2half(v);
    }
    if (threadIdx.x == 0) { br0[rn] = b0[orig]; br1[rn] = b1[orig]; }
}

__global__ void zero_kernel(float* __restrict__ c0, float* __restrict__ c1,
                            __half* __restrict__ zb) {
    int i = blockIdx.x * blockDim.x + threadIdx.x;
    if (i < HB) { c0[i] = 0.f; c1[i] = 0.f; zb[i] = __float2half(0.f); }
}

// ---------------------------------------------------------------------------
// Cell body: one MT(batch)x64(gate) tile of a fused LSTM step on fp16 HMMA.
// (R15-proven: K=64 chunks, 3-stage cp.async pipeline, per-K-group C slabs.)
// ---------------------------------------------------------------------------
template <int MT>
__device__ __forceinline__ void cell_body(
    char* smem, int m0, int tileY,
    const __half* __restrict__ Ah, const __half* __restrict__ Bh,   // h, Whh
    const __half* __restrict__ Ax, const __half* __restrict__ Bx,   // x, Wx
    int ncx, int ldx,
    const float* __restrict__ biasr,
    float* __restrict__ c, float* __restrict__ hf,
    __half* __restrict__ hout) {

    constexpr int A_TILE = A_TILE_BYTES_(MT);
    constexpr int STAGE  = STAGE_BYTES_(MT);
    constexpr int OFF_A  = 0;
    constexpr int OFF_B  = A_TILE;
    constexpr int OFF_BIAS = OFF_BIAS_(MT);
    constexpr int WM = MT / 32;           // M warp-slices (1 or 2)
    constexpr int KS = 8 / (WM * 2);      // K-groups (4 or 2)
    constexpr int KITER = 4 / KS;         // kk slices per warp per chunk
    constexpr int CSLAB = MT * CS_STRIDE; // floats per K-group C slab
    static_assert(WM * 2 * KS == 8, "warp layout");

    const uint32_t sbase = smem_u32(smem);
    const int tid = threadIdx.x;
    const int warp = tid >> 5;
    const int lane = tid & 31;
    const int n0 = tileY * 64;            // reordered weight row base
    const int u0 = tileY * 16;            // unit base
    const int ks = warp % KS;
    const int rem = warp / KS;
    const int wn = rem & 1;               // 0..1 (32-col slices)
    const int wm = rem >> 1;              // 0..WM-1 (32-row slices)

    if (tid < 64)
        *reinterpret_cast<float*>(smem + OFF_BIAS + tid * 4) = biasr[n0 + tid];

    float cf[2][4][4];
#pragma unroll
    for (int mi = 0; mi < 2; mi++)
#pragma unroll
        for (int nj = 0; nj < 4; nj++)
#pragma unroll
            for (int r = 0; r < 4; r++) cf[mi][nj][r] = 0.f;

    const int NC = 8 + ncx;

    auto prefetch = [&](int ch) {
        const __half *aP, *bP;
        int lda, k0;
        if (ch < 8) { aP = Ah; bP = Bh; lda = HID; k0 = ch * 64; }
        else        { aP = Ax; bP = Bx; lda = ldx; k0 = (ch - 8) * 64; }
        const uint32_t st = sbase + (ch % NSTAGE) * STAGE;
#pragma unroll
        for (int i = 0; i < (MT * 8) / NTHREADS; i++) {
            int idx = tid + i * NTHREADS;
            int r = idx >> 3, q = idx & 7;
            uint32_t off = r * ROW_B + q * 16;
            long ao = (long)(m0 + r) * lda + k0 + q * 8;
            CP_ASYNC16(st + OFF_A + off, aP + ao);
        }
#pragma unroll
        for (int i = 0; i < 512 / NTHREADS; i++) {
            int idx = tid + i * NTHREADS;
            int r = idx >> 3, q = idx & 7;
            uint32_t off = r * ROW_B + q * 16;
            long bo = (long)(n0 + r) * lda + k0 + q * 8;
            CP_ASYNC16(st + OFF_B + off, bP + bo);
        }
    };

    prefetch(0); CP_COMMIT();
    prefetch(1); CP_COMMIT();

    for (int ch = 0; ch < NC; ch++) {
        if (ch + 1 < NC) CP_WAIT1(); else CP_WAIT0();
        __syncthreads();                    // publishes chunk ch
        if (ch + 2 < NC) { prefetch(ch + 2); CP_COMMIT(); }

        const uint32_t base = sbase + (ch % NSTAGE) * STAGE;
#pragma unroll
        for (int ki = 0; ki < KITER; ki++) {
            const int kk = (ks * KITER + ki) * 16;
            uint32_t ah[2][4], bh[4][2];
#pragma unroll
            for (int mi = 0; mi < 2; mi++) {
                uint32_t roff =
                    (uint32_t)((wm * 32 + mi * 16 + (lane & 15)) * ROW_B +
                               (kk + (lane >> 4) * 8) * 2);
                LDM4(ah[mi], base + OFF_A + roff);
            }
#pragma unroll
            for (int p = 0; p < 2; p++) {
                uint32_t roff =
                    (uint32_t)((wn * 32 + p * 16 + (lane & 15)) * ROW_B +
                               (kk + (lane >> 4) * 8) * 2);
                uint32_t rb[4];
                LDM4(rb, base + OFF_B + roff);
                bh[p * 2 + 0][0] = rb[0]; bh[p * 2 + 0][1] = rb[2];
                bh[p * 2 + 1][0] = rb[1]; bh[p * 2 + 1][1] = rb[3];
            }
#pragma unroll
            for (int mi = 0; mi < 2; mi++)
#pragma unroll
                for (int nj = 0; nj < 4; nj++)
                    MMA16816F(cf[mi][nj], ah[mi], bh[nj][0], bh[nj][1]);
        }
    }
    __syncthreads();   // all ldmatrix reads done before Cs overwrites stage 0

    // ---- epilogue: per-K-group C slabs (single barrier) ----
    float* Cs = reinterpret_cast<float*>(smem);   // KS slabs of MT x CS_STRIDE
    {
        float* Cg = Cs + ks * CSLAB;
#pragma unroll
        for (int mi = 0; mi < 2; mi++)
#pragma unroll
            for (int nj = 0; nj < 4; nj++) {
                int r = wm * 32 + mi * 16 + (lane >> 2);
                int col = wn * 32 + nj * 8 + (lane & 3) * 2;
                Cg[r * CS_STRIDE + col]           = cf[mi][nj][0];
                Cg[r * CS_STRIDE + col + 1]       = cf[mi][nj][1];
                Cg[(r + 8) * CS_STRIDE + col]     = cf[mi][nj][2];
                Cg[(r + 8) * CS_STRIDE + col + 1] = cf[mi][nj][3];
            }
    }
    __syncthreads();

    const float* Bs = reinterpret_cast<const float*>(smem + OFF_BIAS);
#pragma unroll
    for (int k = 0; k < (MT * 16) / NTHREADS; k++) {
        int id = tid + k * NTHREADS;
        int u = id & 15, bb = id >> 4;        // bb 0..MT-1
        float4 g4 = *reinterpret_cast<const float4*>(&Cs[bb * CS_STRIDE + u * 4]);
#pragma unroll
        for (int g = 1; g < KS; g++) {
            float4 p4 = *reinterpret_cast<const float4*>(
                &Cs[g * CSLAB + bb * CS_STRIDE + u * 4]);
            g4.x += p4.x; g4.y += p4.y; g4.z += p4.z; g4.w += p4.w;
        }
        float gi = sigmoidf_(g4.x + Bs[u * 4 + 0]);
        float gf = sigmoidf_(g4.y + Bs[u * 4 + 1]);
        float gg = tanhf_   (g4.z + Bs[u * 4 + 2]);
        float go = sigmoidf_(g4.w + Bs[u * 4 + 3]);
        int gidx = (m0 + bb) * HID + u0 + u;
        float cn = gf * c[gidx] + gi * gg;
        c[gidx] = cn;
        float hv = go * tanhf_(cn);
        if (hf) hf[gidx] = hv;
        hout[gidx] = __float2half(hv);
    }
}

// ---------------------------------------------------------------------------
// THE persistent kernel: whole network after prep. 256 CTAs, occ 2,
// fast flag-tree grid barriers between dependent phases.
// ---------------------------------------------------------------------------
__global__ void __launch_bounds__(NTHREADS, 2)
lstm_persist(const __half* __restrict__ xp, __half* __restrict__ xd,
             const __half* __restrict__ zb,
             const __half* __restrict__ w0,   const __half* __restrict__ wx0,
             const float* __restrict__ br0,  float* __restrict__ c0,
             const __half* __restrict__ w1hh, const __half* __restrict__ w1ih,
             const float* __restrict__ br1,  float* __restrict__ c1,
             __half* __restrict__ y0, __half* __restrict__ h1,
             __half* __restrict__ h0, float* __restrict__ h1f,
             const float* __restrict__ headW, const float* __restrict__ headb,
             const float* __restrict__ wf,
             float* __restrict__ pred, float* __restrict__ out) {
    extern __shared__ __align__(16) char smem[];
    const int bid = blockIdx.x;
    unsigned gen = *((volatile unsigned*)&g_gen);   // per-launch base

    // ===== encoder: L1 on CTAs 0..127 (4x32 tiles, MT=64), L0 on 128..255 ====
    {
        const bool isL1 = bid < 128;
        const int rem = isL1 ? bid : bid - 128;
        const int m0 = (rem >> 5) * 64;
        const int yt = rem & 31;

        if (!isL1)   // L0(0): A = zeros, X = xp[0]
            cell_body<64>(smem, m0, yt, zb, w0, xp, wx0,
                          1, XPW, br0, c0, nullptr, y0);
        grid_bar(gen);

        for (int t = 0; t < T_HIST; t++) {      // t = 0..149
            if (isL1) {
                const __half* h1p = (t == 0) ? zb : (h1 + ((t + 1) & 1) * HB);
                cell_body<64>(smem, m0, yt, h1p, w1hh,
                              y0 + (size_t)t * HB, w1ih,
                              8, HID, br1, c1, nullptr, h1 + (t & 1) * HB);
            } else if (t < T_HIST - 1) {
                cell_body<64>(smem, m0, yt, y0 + (size_t)t * HB, w0,
                              xp + (size_t)(t + 1) * NB * XPW, wx0,
                              1, XPW, br0, c0, nullptr,
                              y0 + (size_t)(t + 1) * HB);
            }
            grid_bar(gen);
        }
    }

    // ===== decoder: all 256 CTAs (8x32 tiles, MT=32); 3 phases per step =====
    {
        const int m0 = (bid >> 5) * 32;
        const int yt = bid & 31;
        for (int t = 0; t < T_FUT; t++) {
            // L0(t): A = h0 prev (or y0[149]), X = xd
            const __half* hp = (t == 0) ? (y0 + (size_t)(T_HIST - 1) * HB)
                                        : (h0 + ((t + 1) & 1) * HB);
            cell_body<32>(smem, m0, yt, hp, w0, xd, wx0,
                          1, XPW, br0, c0, nullptr, h0 + (t & 1) * HB);
            grid_bar(gen);
            // L1(t): A = h1 prev (enc ended at index 1; read (t+1)&1, write t&1)
            cell_body<32>(smem, m0, yt, h1 + ((t + 1) & 1) * HB, w1hh,
                          h0 + (t & 1) * HB, w1ih,
                          8, HID, br1, c1, h1f, h1 + (t & 1) * HB);
            grid_bar(gen);
            // head: CTA bid handles batch b = bid
            {
                const int b = bid;
                if (threadIdx.x < 128) {
                    int w = threadIdx.x >> 5;
                    int lane = threadIdx.x & 31;
                    const float* hr = h1f + b * HID;
                    const float* wr = headW + w * HID;
                    float s = 0.f;
                    for (int k = lane; k < HID; k += 32)
                        s += __ldcg(hr + k) * wr[k];   // L1-bypass: cross-CTA
#pragma unroll
                    for (int o = 16; o; o >>= 1)
                        s += __shfl_down_sync(0xffffffffu, s, o);
                    if (lane == 0) {
                        float p = pred[b * VEG + w] + s + headb[w];
                        pred[b * VEG + w] = p;
                        out[b * (T_FUT * VEG) + t * VEG + w] = p;
                        xd[b * XPW + w] = __float2half(p);
                    }
                    if (threadIdx.x < WEA && t + 1 < T_FUT)
                        xd[b * XPW + VEG + threadIdx.x] = __float2half(
                            wf[b * (T_FUT * WEA) + (t + 1) * WEA + threadIdx.x]);
                }
            }
            grid_bar(gen);
        }
    }
}

// ---------------------------------------------------------------------------
// Host launcher (single stream — graph-capture safe; ONE main kernel)
// ---------------------------------------------------------------------------
extern "C" void kernel_launch(void* const* d_in, const int* in_sizes, int n_in,
                              void* d_out, int out_size) {
    const float* veg   = (const float*)d_in[0];
    const float* wh    = (const float*)d_in[1];
    const float* wf    = (const float*)d_in[2];
    const float* Wih0  = (const float*)d_in[3];
    const float* Whh0  = (const float*)d_in[4];
    const float* b0    = (const float*)d_in[5];
    const float* Wih1  = (const float*)d_in[6];
    const float* Whh1  = (const float*)d_in[7];
    const float* b1    = (const float*)d_in[8];
    const float* headW = (const float*)d_in[9];
    const float* headb = (const float*)d_in[10];
    float* out = (float*)d_out;

    __half *xp, *xd, *y0, *zb, *h1, *h0;
    __half *w0, *w1hh, *w1ih, *wx0;
    float *pred, *c0, *c1, *h1f, *br0, *br1;
    cudaGetSymbolAddress((void**)&xp,    g_xp);
    cudaGetSymbolAddress((void**)&xd,    g_xd);
    cudaGetSymbolAddress((void**)&pred,  g_pred);
    cudaGetSymbolAddress((void**)&y0,    g_y0);
    cudaGetSymbolAddress((void**)&zb,    g_zb);
    cudaGetSymbolAddress((void**)&c0,    g_c0);
    cudaGetSymbolAddress((void**)&c1,    g_c1);
    cudaGetSymbolAddress((void**)&h1,    g_h1);
    cudaGetSymbolAddress((void**)&h0,    g_h0);
    cudaGetSymbolAddress((void**)&h1f,   g_h1f);
    cudaGetSymbolAddress((void**)&w0,    g_w0);
    cudaGetSymbolAddress((void**)&w1hh,  g_w1hh);
    cudaGetSymbolAddress((void**)&w1ih,  g_w1ih);
    cudaGetSymbolAddress((void**)&wx0,   g_wx0);
    cudaGetSymbolAddress((void**)&br0,   g_br0);
    cudaGetSymbolAddress((void**)&br1,   g_br1);

    cudaFuncSetAttribute(lstm_persist,
                         cudaFuncAttributeMaxDynamicSharedMemorySize,
                         SMEM_TOTAL_(64));

    prep_kernel<<<T_HIST, NB>>>(veg, wh, wf, xp, xd, pred);
    wprep_kernel<<<GROW, 128>>>(Wih0, Whh0, b0, Wih1, Whh1, b1,
                                w0, w1hh, w1ih, wx0, br0, br1);
    zero_kernel<<<(HB + 255) / 256, 256>>>(c0, c1, zb);

    lstm_persist<<<NCTA, NTHREADS, SMEM_TOTAL_(64)>>>(
        xp, xd, zb,
        w0, wx0, br0, c0,
        w1hh, w1ih, br1, c1,
        y0, h1, h0, h1f,
        headW, headb, wf, pred, out);
}